// round 8
// baseline (speedup 1.0000x reference)
#include <cuda_runtime.h>

#define KK 48
#define TT 1024
#define BB 512
#define KBIG (1 << 20)
#define NEG_BIG (-3.0e38f)

typedef unsigned long long ull;

__device__ __forceinline__ ull ffma2(ull a, ull b, ull c) {
    ull d;
    asm("fma.rn.f32x2 %0, %1, %2, %3;" : "=l"(d) : "l"(a), "l"(b), "l"(c));
    return d;
}
__device__ __forceinline__ ull fadd2(ull a, ull b) {
    ull d;
    asm("add.rn.f32x2 %0, %1, %2;" : "=l"(d) : "l"(a), "l"(b));
    return d;
}
__device__ __forceinline__ float hsum2(ull v) {
    float lo, hi;
    asm("mov.b64 {%0, %1}, %2;" : "=f"(lo), "=f"(hi) : "l"(v));
    return lo + hi;
}
__device__ __forceinline__ ull pack2(float lo, float hi) {
    ull d;
    asm("mov.b64 %0, {%1, %2};" : "=l"(d) : "f"(lo), "f"(hi));
    return d;
}

struct Smem {
    __align__(16) float pS[2][3][64];  // sup p, [buf][tier slot][col]
    __align__(16) float pU[2][64];     // unsup p, [buf][col]
    float sS[2][2];                    // [chain][buf] = S
    __align__(8) int flg[2][2];        // [buf][sup warp]
    float ancsm[2];
    int ksm[2][64];
    float rsm[2][64];
    int zkk[2];
    float zrr[2];
};

// CTA = 128 threads = batch b. Warps 0-1: sup chain, warps 2-3: unsup chain.
// Lane owns one column j = tid & 63 (j<48 real, j==48 = ones column -> S).
template <int MODE>
__device__ __forceinline__ void run_batch(
    Smem* sm, const int tid, const int b,
    const float* __restrict__ emissions,
    const void* __restrict__ maskv,
    const void* __restrict__ targetv,
    const float* __restrict__ startp,
    const void* __restrict__ sforbv,
    const float* __restrict__ endp,
    const void* __restrict__ eforbv,
    const float* __restrict__ trans,
    const void* __restrict__ forbv,
    float* __restrict__ out) {
    const unsigned FULL = 0xffffffffu;
    const int lane = tid & 31;
    const int warpid = tid >> 5;
    const int c = tid >> 6;        // chain: 0 sup, 1 unsup
    const bool sup = (c == 0);
    const int w01 = warpid & 1;    // warp index within chain
    const int j = tid & 63;        // owned column

    const unsigned char* f8 = (const unsigned char*)forbv;
    const unsigned int* f32 = (const unsigned int*)forbv;
#define FRB(x) (MODE ? (f8[x] != 0) : (f32[x] != 0u))
    const unsigned char* tg8 = (const unsigned char*)targetv + (MODE ? (size_t)b * TT * KK : 0);
    const unsigned int* tg32 = (const unsigned int*)targetv + (MODE ? 0 : (size_t)b * TT * KK);
    const unsigned char* sf8 = (const unsigned char*)sforbv;
    const unsigned int* sf32 = (const unsigned int*)sforbv;
    const unsigned char* ef8 = (const unsigned char*)eforbv;
    const unsigned int* ef32 = (const unsigned int*)eforbv;
#define TGT(off) (MODE ? (tg8[off] != 0) : (tg32[off] != 0u))
#define SFB(s)   (MODE ? (sf8[s] != 0) : (sf32[s] != 0u))
#define EFB(s)   (MODE ? (ef8[s] != 0) : (ef32[s] != 0u))

    // ---- E column j (packed source pairs); j==48 -> ones column ----
    ull e[24];
#pragma unroll
    for (int k = 0; k < 24; k++) {
        float a = 0.f, bb = 0.f;
        if (j < KK) {
            const int i0 = 2 * k, i1 = 2 * k + 1;
            a = FRB(i0 * KK + j) ? 0.f : __expf(trans[i0 * KK + j]);
            bb = FRB(i1 * KK + j) ? 0.f : __expf(trans[i1 * KK + j]);
        } else if (j == 48) {
            a = 1.f;
            bb = 1.f;
        }
        e[k] = pack2(a, bb);
    }

    // ---- sequence length (each warp computes redundantly) ----
    int len;
    if (MODE == 1) {
        const unsigned int* mrow =
            reinterpret_cast<const unsigned int*>((const unsigned char*)maskv + (size_t)b * TT);
        int cnt = 0;
#pragma unroll
        for (int k2 = 0; k2 < 8; k2++)
            cnt = __dp4a((int)mrow[lane + k2 * 32], 0x01010101, cnt);
#pragma unroll
        for (int o = 16; o > 0; o >>= 1) cnt += __shfl_xor_sync(FULL, cnt, o);
        len = cnt;
    } else {
        const unsigned int* mrow = (const unsigned int*)maskv + (size_t)b * TT;
        int cnt = 0;
#pragma unroll
        for (int k2 = 0; k2 < 32; k2++) cnt += (mrow[lane + k2 * 32] != 0u) ? 1 : 0;
#pragma unroll
        for (int o = 16; o > 0; o >>= 1) cnt += __shfl_xor_sync(FULL, cnt, o);
        len = cnt;
    }
    const int stop = len - 1;  // len >= 512

    const float* emb = emissions + (size_t)b * TT * KK;

    // ---- t=0 init ----
    float vcur = 0.f;
    int dscur = 0;
    int mks = 0;
    float anc = 0.f;
    if (j < KK) {
        float em0 = emb[j];
        if (sup) {
            bool m0 = !TGT(j);
            bool sf = SFB(j);
            dscur = (m0 ? 1 : 0) + (sf ? 1 : 0);
            vcur = __expf((m0 ? 0.f : em0) + (sf ? 0.f : startp[j]));
        } else {
            vcur = __expf(em0 + startp[j]);
        }
    }
    if (sup) {
        sm->pS[0][0][j] = (dscur == 0) ? vcur : 0.f;
        sm->pS[0][1][j] = (dscur == 1) ? vcur : 0.f;
        sm->pS[0][2][j] = (dscur == 2) ? vcur : 0.f;
        unsigned b0 = __ballot_sync(FULL, (j < KK) && dscur == 0);
        unsigned b1 = __ballot_sync(FULL, (j < KK) && dscur == 1);
        if (lane == 0) sm->flg[0][w01] = (b0 ? 1 : 0) | (b1 ? 2 : 0);
    } else {
        sm->pU[0][j] = vcur;
    }
    if (j == 48) sm->sS[c][0] = 1.0f;
    __syncthreads();

    int buf = 0;

    // ---- prefetch stages (distance 2): g = exp(em), msk ----
    float g0 = 0.f, g1 = 0.f;
    bool k0f = false, k1f = false;
#define PRELOAD(G, M, ROW)                                            \
    {                                                                 \
        if (j < KK) {                                                 \
            G = __expf(emb[(size_t)(ROW)*KK + j]);                    \
            if (sup) M = !TGT((size_t)(ROW)*KK + j);                  \
        }                                                             \
    }
    PRELOAD(g0, k0f, 1)
    if (stop >= 2) PRELOAD(g1, k1f, 2)

#define STEP(G, MSK)                                                          \
    do {                                                                      \
        const float Sprev = sm->sS[c][buf];                                   \
        const float rv = __fdividef(1.f, Sprev);                              \
        int m = 0;                                                            \
        if (sup) {                                                            \
            int2 ff = *(const int2*)&sm->flg[buf][0];                         \
            int f = ff.x | ff.y;                                              \
            m = (f & 1) ? 0 : ((f & 2) ? 1 : 2);                              \
            mks += m;                                                         \
        }                                                                     \
        const float* base = sup ? &sm->pS[buf][m][0] : &sm->pU[buf][0];       \
        ull A0 = 0, A1 = 0, A2 = 0, A3 = 0;                                   \
        {                                                                     \
            const ulonglong2* q = (const ulonglong2*)base;                    \
            _Pragma("unroll") for (int k2 = 0; k2 < 6; k2++) {                \
                ulonglong2 x = q[2 * k2];                                     \
                ulonglong2 y = q[2 * k2 + 1];                                 \
                A0 = ffma2(x.x, e[4 * k2 + 0], A0);                           \
                A1 = ffma2(x.y, e[4 * k2 + 1], A1);                           \
                A2 = ffma2(y.x, e[4 * k2 + 2], A2);                           \
                A3 = ffma2(y.y, e[4 * k2 + 3], A3);                           \
            }                                                                 \
        }                                                                     \
        const float A = hsum2(fadd2(fadd2(A0, A1), fadd2(A2, A3)));           \
        const int nb = buf ^ 1;                                               \
        if (sup) {                                                            \
            bool pro = !(A > 0.f);                                            \
            float bs = pro ? 1.f : A * rv;                                    \
            float v = (MSK) ? bs : bs * (G);                                  \
            int nds = (pro ? 1 : 0) + ((MSK) ? 1 : 0);                        \
            sm->pS[nb][0][j] = (nds == 0) ? v : 0.f;                          \
            sm->pS[nb][1][j] = (nds == 1) ? v : 0.f;                          \
            sm->pS[nb][2][j] = (nds == 2) ? v : 0.f;                          \
            vcur = v;                                                         \
            dscur = nds;                                                      \
            unsigned b0 = __ballot_sync(FULL, (j < KK) && nds == 0);          \
            unsigned b1 = __ballot_sync(FULL, (j < KK) && nds == 1);          \
            if (lane == 0) sm->flg[nb][w01] = (b0 ? 1 : 0) | (b1 ? 2 : 0);    \
        } else {                                                              \
            float v = A * rv * (G);                                           \
            sm->pU[nb][j] = v;                                                \
            vcur = v;                                                         \
        }                                                                     \
        if (j == 48) {                                                        \
            anc += __logf(Sprev);                                             \
            sm->sS[c][nb] = A;                                                \
        }                                                                     \
        __syncthreads();                                                      \
        buf ^= 1;                                                             \
    } while (0)

    int t = 1;
    for (; t + 1 <= stop; t += 2) {
        {
            float gg = g0;
            bool mm = k0f;
            int tn = t + 2;
            if (tn > stop) tn = stop;
            PRELOAD(g0, k0f, tn)
            STEP(gg, mm);
        }
        {
            float gg = g1;
            bool mm = k1f;
            int tn = t + 3;
            if (tn > stop) tn = stop;
            PRELOAD(g1, k1f, tn)
            STEP(gg, mm);
        }
    }
    if (t <= stop) { STEP(g0, k0f); }

    // ---- epilogue ----
    if (j == 48) sm->ancsm[c] = anc;
    __syncthreads();
    {
        const float ancv = sm->ancsm[c];
        int kj = KBIG;
        float rj = NEG_BIG;
        if (j < KK) {
            bool ef = EFB(j);
            kj = (sup ? (mks + dscur) : 0) + (ef ? 1 : 0);
            rj = ancv + __logf(vcur) + (ef ? 0.f : endp[j]);
        }
        sm->ksm[c][j] = kj;
        sm->rsm[c][j] = rj;
    }
    __syncthreads();
    if ((warpid & 1) == 0) {
        const int cc = warpid >> 1;
        int k0 = sm->ksm[cc][lane], k1 = sm->ksm[cc][lane + 32];
        float r0 = sm->rsm[cc][lane], r1 = sm->rsm[cc][lane + 32];
        int fk;
        float fr;
        if (k0 < k1) { fk = k0; fr = r0; }
        else if (k1 < k0) { fk = k1; fr = r1; }
        else { fk = k0; fr = fmaxf(r0, r1); }
#pragma unroll
        for (int o = 16; o > 0; o >>= 1) {
            int ok = __shfl_xor_sync(FULL, fk, o);
            float orr = __shfl_xor_sync(FULL, fr, o);
            if (ok < fk) { fk = ok; fr = orr; }
            else if (ok == fk) fr = fmaxf(fr, orr);
        }
        float ss = ((k0 == fk) ? __expf(r0 - fr) : 0.f) +
                   ((k1 == fk) ? __expf(r1 - fr) : 0.f);
#pragma unroll
        for (int o = 16; o > 0; o >>= 1) ss += __shfl_xor_sync(FULL, ss, o);
        if (lane == 0) {
            sm->zkk[cc] = fk;
            sm->zrr[cc] = fr + __logf(ss);
        }
    }
    __syncthreads();
    if (tid == 0) {
        double v = -1.0e7 * (double)(sm->zkk[1] - sm->zkk[0]) +
                   (double)(sm->zrr[1] - sm->zrr[0]);
        out[b] = (float)v;
    }
#undef FRB
#undef TGT
#undef SFB
#undef EFB
#undef PRELOAD
#undef STEP
}

__global__ void __launch_bounds__(128) crf_kernel(
    const float* __restrict__ emissions,
    const void* __restrict__ maskv,
    const void* __restrict__ targetv,
    const float* __restrict__ startp,
    const void* __restrict__ sforbv,
    const float* __restrict__ endp,
    const void* __restrict__ eforbv,
    const float* __restrict__ trans,
    const void* __restrict__ forbv,
    float* __restrict__ out) {
    __shared__ Smem sm;
    const int tid = threadIdx.x;
    const int b = blockIdx.x;
    unsigned w0 = ((const unsigned int*)maskv)[0];
    if (w0 == 0x01010101u)
        run_batch<1>(&sm, tid, b, emissions, maskv, targetv, startp, sforbv,
                     endp, eforbv, trans, forbv, out);
    else
        run_batch<0>(&sm, tid, b, emissions, maskv, targetv, startp, sforbv,
                     endp, eforbv, trans, forbv, out);
}

extern "C" void kernel_launch(void* const* d_in, const int* in_sizes, int n_in,
                              void* d_out, int out_size) {
    const float* emissions = (const float*)d_in[0];
    const void* mask       = d_in[1];
    const void* target     = d_in[2];
    const float* trans     = (const float*)d_in[3];
    const float* start_t   = (const float*)d_in[4];
    const float* end_t     = (const float*)d_in[5];
    const void* forb       = d_in[6];
    const void* sforb      = d_in[7];
    const void* eforb      = d_in[8];

    crf_kernel<<<BB, 128>>>(emissions, mask, target, start_t, sforb, end_t,
                            eforb, trans, forb, (float*)d_out);
}